// round 17
// baseline (speedup 1.0000x reference)
#include <cuda_runtime.h>
#include <cuda_bf16.h>
#include <math.h>

#define NBATCH 2
#define NLR    4096
#define NPTS   (NBATCH*NLR)
#define SPLITS 16
#define KT     32
#define RT     128
#define KHL    48
#define GP2    168

#define W3J_TOTAL   13318
#define W3J_OUT_OFF 2670

__device__ float d_feat0[NPTS*22];
__device__ float d_feat1[NPTS*22];
__device__ float d_qvT[22*NPTS];
__device__ __align__(16) float d_khl[NPTS*KHL];
__device__ __align__(16) float d_gv2[(NPTS/2)*GP2];
__device__ __align__(16) float d_part[SPLITS*NPTS*68];
__device__ float d_G   [66*NPTS];
__device__ float d_sh  [NLR*6];
__device__ float d_eb  [2*NLR];
__device__ float d_w3j [W3J_TOTAL];
__device__ float d_coef[2*8*3];

__constant__ int PATH_L[14][3] = {
  {4,0,4},{4,2,4},{6,2,4},{6,0,6},{4,2,6},{6,2,6},
  {4,4,4},{4,6,4},{6,4,4},{6,6,4},{4,4,6},{4,6,6},{6,4,6},{6,6,6}};
__constant__ int PATH_OFF[15] = {
  0,81,486,1071,1240,1825,2670,3399,4452,5505,7026,8079,9600,11121,13318};

// ---------------- tf32 / async helpers ----------------
__device__ __forceinline__ unsigned tf32bits(float x){
  unsigned u;
  asm("cvt.rna.tf32.f32 %0, %1;" : "=r"(u) : "f"(x));
  return u;
}
__device__ __forceinline__ float tf32r(float x){
  return __uint_as_float(tf32bits(x));
}
__device__ __forceinline__ void mma_tf32(float* c,
    unsigned a0, unsigned a1, unsigned a2, unsigned a3,
    unsigned b0, unsigned b1){
  asm volatile(
    "mma.sync.aligned.m16n8k8.row.col.f32.tf32.tf32.f32 "
    "{%0,%1,%2,%3}, {%4,%5,%6,%7}, {%8,%9}, {%0,%1,%2,%3};"
    : "+f"(c[0]), "+f"(c[1]), "+f"(c[2]), "+f"(c[3])
    : "r"(a0), "r"(a1), "r"(a2), "r"(a3), "r"(b0), "r"(b1));
}
__device__ __forceinline__ void cpa16(unsigned s, const void* g){
  asm volatile("cp.async.ca.shared.global [%0], [%1], 16;" :: "r"(s), "l"(g));
}
__device__ __forceinline__ void cpa_commit(){
  asm volatile("cp.async.commit_group;" ::: "memory");
}
__device__ __forceinline__ void cpa_wait0(){
  asm volatile("cp.async.wait_group 0;" ::: "memory");
}

// ---------------- W3J (real Wigner/CG) ----------------
struct Cpx { double re, im; };

__device__ __forceinline__ double dev_cg(int j1,int m1,int j2,int m2,int j3,int m3,const double* f){
  if (m1+m2 != m3) return 0.0;
  if (j3 < abs(j1-j2) || j3 > j1+j2) return 0.0;
  double pref = sqrt((2.0*j3+1.0)*f[j3+j1-j2]*f[j3-j1+j2]*f[j1+j2-j3]/f[j1+j2+j3+1]);
  pref *= sqrt(f[j3+m3]*f[j3-m3]*f[j1-m1]*f[j1+m1]*f[j2-m2]*f[j2+m2]);
  double s = 0.0;
  int kmax = j1+j2-j3;
  for (int k=0;k<=kmax;k++){
    int a3=j1-m1-k, a4=j2+m2-k, a5=j3-j2+m1+k, a6=j3-j1-m2+k;
    if (a3<0||a4<0||a5<0||a6<0) continue;
    double t = 1.0/(f[k]*f[kmax-k]*f[a3]*f[a4]*f[a5]*f[a6]);
    s += (k&1)? -t : t;
  }
  return pref*s;
}

__device__ __forceinline__ int unz(int l, int r, int* cols, Cpx* vals){
  const double s2 = 0.70710678118654752440;
  if (r == l){ cols[0]=l; vals[0]=Cpx{1.0,0.0}; return 1; }
  if (r > l){ int m=r-l; double sg=(m&1)?-1.0:1.0;
    cols[0]=l+m; vals[0]=Cpx{sg*s2,0.0};
    cols[1]=l-m; vals[1]=Cpx{s2,0.0}; return 2; }
  int m=l-r; double sg=(m&1)?-1.0:1.0;
  cols[0]=l-m; vals[0]=Cpx{0.0,s2};
  cols[1]=l+m; vals[1]=Cpx{0.0,-sg*s2}; return 2;
}

__device__ __forceinline__ Cpx uent(int l,int r,int c){
  const double s2 = 0.70710678118654752440;
  Cpx z = Cpx{0.0,0.0};
  if (r==l){ if (c==l) z = Cpx{1.0,0.0}; return z; }
  if (r>l){ int m=r-l; double sg=(m&1)?-1.0:1.0;
    if (c==l+m) z = Cpx{sg*s2,0.0}; else if (c==l-m) z = Cpx{s2,0.0}; return z; }
  int m=l-r; double sg=(m&1)?-1.0:1.0;
  if (c==l-m) z = Cpx{0.0,s2}; else if (c==l+m) z = Cpx{0.0,-sg*s2};
  return z;
}

__global__ void k_w3j(){
  int path = blockIdx.x;
  int l1=PATH_L[path][0], l2=PATH_L[path][1], l3=PATH_L[path][2];
  int d1=2*l1+1, d2=2*l2+1, d3=2*l3+1;
  int off=PATH_OFF[path];
  int total=d1*d2*d3;
  __shared__ double Cc[169];
  __shared__ double red[256];
  int tid=threadIdx.x;
  double fct[20]; fct[0]=1.0;
  for (int i=1;i<20;i++) fct[i]=fct[i-1]*(double)i;
  for (int e=tid; e<d1*d2; e+=256){
    int a=e/d2, b=e%d2;
    int m1=a-l1, m2=b-l2, m3=m1+m2;
    Cc[e] = (abs(m3)<=l3) ? dev_cg(l1,m1,l2,m2,l3,m3,fct) : 0.0;
  }
  __syncthreads();
  double tv[9]; double ss=0.0; int cnt=0;
  for (int e=tid; e<total; e+=256){
    int i=e/(d2*d3); int j=(e/d3)%d2; int k=e%d3;
    int c1[2], c2[2]; Cpx u1[2], u2[2];
    int n1 = unz(l1,i,c1,u1);
    int n2 = unz(l2,j,c2,u2);
    double re=0.0;
    for (int ii=0;ii<n1;ii++)
      for (int jj=0;jj<n2;jj++){
        int c = c1[ii]-l1 + c2[jj]-l2 + l3;
        if (c<0 || c>2*l3) continue;
        Cpx u3 = uent(l3,k,c);
        if (u3.re==0.0 && u3.im==0.0) continue;
        double cgv = Cc[c1[ii]*d2 + c2[jj]];
        if (cgv==0.0) continue;
        double pr = u1[ii].re*u2[jj].re - u1[ii].im*u2[jj].im;
        double pi = u1[ii].re*u2[jj].im + u1[ii].im*u2[jj].re;
        re += (pr*u3.re + pi*u3.im)*cgv;
      }
    tv[cnt++]=re; ss+=re*re;
  }
  red[tid]=ss; __syncthreads();
  for (int s=128;s>0;s>>=1){ if (tid<s) red[tid]+=red[tid+s]; __syncthreads(); }
  double rnorm = rsqrt(red[0]);
  cnt=0;
  for (int e=tid; e<total; e+=256) d_w3j[off+e] = (float)(tv[cnt++]*rnorm);
}

// ---------------- fused spherical harmonics / bias + coefficients ----------
__global__ void k_shcoef(const float* __restrict__ pbw, const float* __restrict__ pbb,
                         const float* __restrict__ liw4, const float* __restrict__ liw6,
                         const float* __restrict__ tvw,  const float* __restrict__ tow,
                         const float* __restrict__ low4, const float* __restrict__ low6){
  int tid = threadIdx.x;
  if (blockIdx.x < 16){
    int n = blockIdx.x*256 + tid;
    int h=n>>6, w=n&63;
    double y = -1.0 + 2.0*(double)h/63.0;
    double x = -1.0 + 2.0*(double)w/63.0;
    double r = sqrt(x*x+y*y); if (r < 1e-8) r = 1e-8;
    double xn=x/r, yn=y/r;
    const double c0=0.28209479177387814, c2=1.0925484305920792, c20=0.31539156525252005;
    float sh[6];
    sh[0]=(float)c0;
    sh[1]=(float)(c2*xn*yn);
    sh[2]=0.0f;
    sh[3]=(float)(-c20);
    sh[4]=0.0f;
    sh[5]=(float)(0.5*c2*(xn*xn-yn*yn));
    #pragma unroll
    for (int i=0;i<6;i++) d_sh[n*6+i]=sh[i];
    for (int blk=0;blk<2;blk++){
      float b = pbb[blk];
      #pragma unroll
      for (int i=0;i<6;i++) b = fmaf(sh[i], pbw[blk*6+i], b);
      d_eb[blk*NLR+n]=expf(b);
    }
    return;
  }
  __shared__ float a_s[96];
  if (tid < 96){
    int c = tid & 7; int pp = (tid>>3)%6; int blk = tid/48;
    const float* liw = (pp==0||pp==1||pp==4) ? (liw4+blk*8) : (liw6+blk*8);
    float s=0.f;
    for (int u=0;u<8;u++) s = fmaf(liw[u], tvw[((blk*6+pp)*8+u)*8 + c], s);
    a_s[tid]=s;
  }
  __syncthreads();
  if (tid < 16){
    int q = tid&7, blk = tid>>3;
    const float* liw = (q==0||q==1||q==4||q==5)? (liw4+blk*8) : (liw6+blk*8);
    const float* low = (q<4)? (low4+blk*8) : (low6+blk*8);
    float b[8];
    #pragma unroll
    for (int v=0;v<8;v++){
      float s=0.f;
      for (int u=0;u<8;u++){
        float lu = liw[u];
        for (int w=0;w<8;w++)
          s = fmaf(lu*tow[(((blk*8+q)*8+u)*8+v)*8+w], low[w], s);
      }
      b[v]=s;
    }
    int pbase = (q&1)? 3 : 0;
    const float invs = (1.0f/sqrtf(24.0f)) * (1.0f/16.0f) * (1.0f/sqrtf(8.0f));
    for (int pp=0;pp<3;pp++){
      float s=0.f;
      #pragma unroll
      for (int v=0;v<8;v++) s = fmaf(b[v], a_s[(blk*6+pbase+pp)*8 + v], s);
      d_coef[(blk*8+q)*3+pp] = s*invs;
    }
  }
}

// ---------------- per-point prep (featinit folded for blk 0) ---------------
__global__ void __launch_bounds__(64) k_prepare(const float* __restrict__ in4,
                                                const float* __restrict__ in6,
                                                const float* __restrict__ ls4,
                                                const float* __restrict__ ls6,
                                                int blk, int sel){
  __shared__ float wv[W3J_OUT_OFF];
  int tid = threadIdx.x;
  for (int i=tid;i<W3J_OUT_OFF;i+=64) wv[i]=d_w3j[i];
  __syncthreads();
  int p = blockIdx.x*64 + tid;
  float f[22];
  float s4=0.f, s6=0.f;
  if (blk==0){
    #pragma unroll
    for (int i=0;i<9;i++){ f[i]=in4[p*9+i]; s4=fmaf(f[i],f[i],s4); d_feat0[p*22+i]=f[i]; }
    #pragma unroll
    for (int i=0;i<13;i++){ f[9+i]=in6[p*13+i]; s6=fmaf(f[9+i],f[9+i],s6); d_feat0[p*22+9+i]=f[9+i]; }
  } else {
    const float* fin = sel ? d_feat1 : d_feat0;
    #pragma unroll
    for (int i=0;i<9;i++){ f[i]=fin[p*22+i]; s4=fmaf(f[i],f[i],s4); }
    #pragma unroll
    for (int i=9;i<22;i++){ f[i]=fin[p*22+i]; s6=fmaf(f[i],f[i],s6); }
  }
  float inv4=1.f/fmaxf(sqrtf(s4),1e-12f);
  float inv6=1.f/fmaxf(sqrtf(s6),1e-12f);
  float e4=expf(ls4[blk]), e6=expf(ls6[blk]);
  {
    float kh[24], kl[24];
    #pragma unroll
    for (int i=0;i<9;i++){
      float kk=f[i]*inv4;
      d_qvT[i*NPTS+p]=kk*e4;
      kh[i]=tf32r(kk); kl[i]=tf32r(kk-kh[i]);
    }
    #pragma unroll
    for (int i=9;i<22;i++){
      float kk=f[i]*inv6;
      d_qvT[i*NPTS+p]=kk*e6;
      kh[i]=tf32r(kk); kl[i]=tf32r(kk-kh[i]);
    }
    kh[22]=0.f; kh[23]=0.f; kl[22]=0.f; kl[23]=0.f;
    float4* dst = (float4*)(d_khl + (size_t)p*KHL);
    #pragma unroll
    for (int ks=0;ks<3;ks++)
      #pragma unroll
      for (int j=0;j<4;j++)
        dst[ks*4+j] = make_float4(kh[ks*8+j], kh[ks*8+j+4], kl[ks*8+j], kl[ks*8+j+4]);
  }
  int n = p & (NLR-1);
  float ebv = d_eb[blk*NLR+n];
  float sh0=d_sh[n*6];
  float sh2[5];
  #pragma unroll
  for (int j=0;j<5;j++) sh2[j]=d_sh[n*6+1+j];
  float gv[84];
  #pragma unroll
  for (int k=67;k<84;k++) gv[k]=0.f;
  { float a[9];
    #pragma unroll
    for (int k=0;k<9;k++) a[k]=0.f;
    #pragma unroll 1
    for (int i=0;i<9;i++){ float fi=f[i];
      #pragma unroll
      for (int k=0;k<9;k++) a[k]=fmaf(fi,wv[i*9+k],a[k]); }
    #pragma unroll
    for (int k=0;k<9;k++) gv[k]=tf32r(a[k]*sh0*ebv); }
  { float a[9];
    #pragma unroll
    for (int k=0;k<9;k++) a[k]=0.f;
    #pragma unroll 1
    for (int i=0;i<9;i++){ float fi=f[i];
      #pragma unroll 1
      for (int j=0;j<5;j++){ float c=fi*sh2[j];
        #pragma unroll
        for (int k=0;k<9;k++) a[k]=fmaf(c,wv[81+(i*5+j)*9+k],a[k]); } }
    #pragma unroll
    for (int k=0;k<9;k++) gv[9+k]=tf32r(a[k]*ebv); }
  { float a[9];
    #pragma unroll
    for (int k=0;k<9;k++) a[k]=0.f;
    #pragma unroll 1
    for (int i=0;i<13;i++){ float fi=f[9+i];
      #pragma unroll 1
      for (int j=0;j<5;j++){ float c=fi*sh2[j];
        #pragma unroll
        for (int k=0;k<9;k++) a[k]=fmaf(c,wv[486+(i*5+j)*9+k],a[k]); } }
    #pragma unroll
    for (int k=0;k<9;k++) gv[18+k]=tf32r(a[k]*ebv); }
  { float a[13];
    #pragma unroll
    for (int k=0;k<13;k++) a[k]=0.f;
    #pragma unroll 1
    for (int i=0;i<13;i++){ float fi=f[9+i];
      #pragma unroll
      for (int k=0;k<13;k++) a[k]=fmaf(fi,wv[1071+i*13+k],a[k]); }
    #pragma unroll
    for (int k=0;k<13;k++) gv[27+k]=tf32r(a[k]*sh0*ebv); }
  { float a[13];
    #pragma unroll
    for (int k=0;k<13;k++) a[k]=0.f;
    #pragma unroll 1
    for (int i=0;i<9;i++){ float fi=f[i];
      #pragma unroll 1
      for (int j=0;j<5;j++){ float c=fi*sh2[j];
        #pragma unroll
        for (int k=0;k<13;k++) a[k]=fmaf(c,wv[1240+(i*5+j)*13+k],a[k]); } }
    #pragma unroll
    for (int k=0;k<13;k++) gv[40+k]=tf32r(a[k]*ebv); }
  { float a[13];
    #pragma unroll
    for (int k=0;k<13;k++) a[k]=0.f;
    #pragma unroll 1
    for (int i=0;i<13;i++){ float fi=f[9+i];
      #pragma unroll 1
      for (int j=0;j<5;j++){ float c=fi*sh2[j];
        #pragma unroll
        for (int k=0;k<13;k++) a[k]=fmaf(c,wv[1825+(i*5+j)*13+k],a[k]); } }
    #pragma unroll
    for (int k=0;k<13;k++) gv[53+k]=tf32r(a[k]*ebv); }
  gv[66]=tf32r(ebv);
  {
    float* dst = d_gv2 + (size_t)(p>>1)*GP2 + (p&1);
    #pragma unroll 1
    for (int c=0;c<84;c++) dst[c*2] = gv[c];
  }
}

// ---------------- attention: full-HMMA, packed operands, cp.async ----------
__global__ void __launch_bounds__(256,3) k_attn(){
  __shared__ float Qs [24*RT];            // 12288 B
  __shared__ float Kh [2][KT*KHL];        // 2x6144 B
  __shared__ float Gp [2][(KT/2)*GP2];    // 2x10752 B
  const int tid = threadIdx.x;
  const int w = tid>>5, l = tid&31;
  const int batch = blockIdx.y, split = blockIdx.z;
  const int prow = batch*NLR + blockIdx.x*RT;
  const int m0 = batch*NLR + split*(NLR/SPLITS);
  const int ntiles = (NLR/SPLITS)/KT;

  {
    unsigned sK = (unsigned)__cvta_generic_to_shared(&Kh[0][0]);
    unsigned sG = (unsigned)__cvta_generic_to_shared(&Gp[0][0]);
    for (int i=tid;i<KT*KHL/4;i+=256)
      cpa16(sK + i*16, d_khl + (size_t)m0*KHL + i*4);
    for (int i=tid;i<(KT/2)*GP2/4;i+=256)
      cpa16(sG + i*16, d_gv2 + (size_t)(m0>>1)*GP2 + i*4);
    cpa_commit();
  }
  for (int i=tid;i<24*RT;i+=256){
    int kd=i>>7, r=i&127;
    Qs[i] = (kd<22)? d_qvT[kd*NPTS + prow + r] : 0.f;
  }
  cpa_wait0();
  __syncthreads();

  const int r0 = 16*w + (l>>2);
  const int lj = l & 3;
  unsigned qh[3][4], ql[3][4];
  #pragma unroll
  for (int ks=0;ks<3;ks++){
    float v0 = Qs[(ks*8+lj)*RT + r0];
    float v1 = Qs[(ks*8+lj)*RT + r0+8];
    float v2 = Qs[(ks*8+lj+4)*RT + r0];
    float v3 = Qs[(ks*8+lj+4)*RT + r0+8];
    qh[ks][0]=tf32bits(v0); ql[ks][0]=tf32bits(v0-__uint_as_float(qh[ks][0]));
    qh[ks][1]=tf32bits(v1); ql[ks][1]=tf32bits(v1-__uint_as_float(qh[ks][1]));
    qh[ks][2]=tf32bits(v2); ql[ks][2]=tf32bits(v2-__uint_as_float(qh[ks][2]));
    qh[ks][3]=tf32bits(v3); ql[ks][3]=tf32bits(v3-__uint_as_float(qh[ks][3]));
  }

  float accd[9][4];
  #pragma unroll
  for (int n=0;n<9;n++){
    #pragma unroll
    for (int c=0;c<4;c++) accd[n][c]=0.f;
  }

  for (int t=0;t<ntiles;t++){
    const int b = t&1;
    if (t+1<ntiles){
      const int mb = m0 + (t+1)*KT;
      unsigned sK = (unsigned)__cvta_generic_to_shared(&Kh[b^1][0]);
      unsigned sG = (unsigned)__cvta_generic_to_shared(&Gp[b^1][0]);
      for (int i=tid;i<KT*KHL/4;i+=256)
        cpa16(sK + i*16, d_khl + (size_t)mb*KHL + i*4);
      for (int i=tid;i<(KT/2)*GP2/4;i+=256)
        cpa16(sG + i*16, d_gv2 + (size_t)(mb>>1)*GP2 + i*4);
      cpa_commit();
    }
    #pragma unroll
    for (int kg=0;kg<4;kg++){
      float sa[4], sb[4], scc[4];
      #pragma unroll
      for (int i=0;i<4;i++){ sa[i]=0.f; sb[i]=0.f; scc[i]=0.f; }
      const float* kbase = &Kh[b][(kg*8 + (l>>2))*KHL + lj*4];
      #pragma unroll
      for (int ks=0;ks<3;ks++){
        float4 kv = *(const float4*)(kbase + ks*16);
        unsigned b0h=__float_as_uint(kv.x), b1h=__float_as_uint(kv.y);
        unsigned b0l=__float_as_uint(kv.z), b1l=__float_as_uint(kv.w);
        mma_tf32(sa,  qh[ks][0],qh[ks][1],qh[ks][2],qh[ks][3], b0h,b1h);
        mma_tf32(sb,  qh[ks][0],qh[ks][1],qh[ks][2],qh[ks][3], b0l,b1l);
        mma_tf32(scc, ql[ks][0],ql[ks][1],ql[ks][2],ql[ks][3], b0h,b1h);
      }
      float s0 = sa[0]+(sb[0]+scc[0]);
      float s1 = sa[1]+(sb[1]+scc[1]);
      float s2 = sa[2]+(sb[2]+scc[2]);
      float s3 = sa[3]+(sb[3]+scc[3]);
      unsigned a0 = tf32bits(__expf(s0));
      unsigned a1 = tf32bits(__expf(s2));
      unsigned a2 = tf32bits(__expf(s1));
      unsigned a3 = tf32bits(__expf(s3));
      const float* gbase = &Gp[b][(kg*4 + lj)*GP2 + (l>>2)*2];
      #pragma unroll
      for (int n=0;n<9;n++){
        float2 gp2 = *(const float2*)(gbase + n*16);
        mma_tf32(accd[n], a0,a1,a2,a3,
                 __float_as_uint(gp2.x), __float_as_uint(gp2.y));
      }
    }
    if (t+1<ntiles) cpa_wait0();
    __syncthreads();
  }
  {
    const int p0 = prow + r0;
    const int p1 = p0 + 8;
    float* base0 = d_part + ((size_t)split*NPTS + p0)*68;
    float* base1 = d_part + ((size_t)split*NPTS + p1)*68;
    #pragma unroll
    for (int n=0;n<9;n++){
      int col = n*8 + 2*lj;
      if (col < 68){
        *(float2*)(base0 + col) = make_float2(accd[n][0], accd[n][1]);
        *(float2*)(base1 + col) = make_float2(accd[n][2], accd[n][3]);
      }
    }
  }
}

// ---------------- coalesced split reduce (warp per point) ------------------
__global__ void k_reduce(){
  const int lane = threadIdx.x & 31;
  const int p = blockIdx.x*8 + (threadIdx.x>>5);
  float4 acc = make_float4(0.f,0.f,0.f,0.f);
  if (lane < 17){
    #pragma unroll 4
    for (int sp=0;sp<SPLITS;sp++){
      float4 v = *(const float4*)(d_part + ((size_t)sp*NPTS + p)*68 + lane*4);
      acc.x+=v.x; acc.y+=v.y; acc.z+=v.z; acc.w+=v.w;
    }
  }
  float den = __shfl_sync(0xffffffffu, acc.z, 16);
  float inv = 1.f/den;
  if (lane < 17){
    int c = lane*4;
    if (c   < 66) d_G[(c  )*NPTS+p] = acc.x*inv;
    if (c+1 < 66) d_G[(c+1)*NPTS+p] = acc.y*inv;
    if (c+2 < 66) d_G[(c+2)*NPTS+p] = acc.z*inv;
    if (c+3 < 66) d_G[(c+3)*NPTS+p] = acc.w*inv;
  }
}

// ---------------- per-point output tensor products ----------------
template<int D1,int D2,int D3>
__device__ __forceinline__ void qpath(const float* __restrict__ w3, const float* __restrict__ f,
                                      int p, float c0, float c1, float c2,
                                      int g0, int g1, int g2, float* out){
  #pragma unroll 1
  for (int j=0;j<D2;j++){
    float gm = c0*d_G[(g0+j)*NPTS+p] + c1*d_G[(g1+j)*NPTS+p] + c2*d_G[(g2+j)*NPTS+p];
    #pragma unroll
    for (int i=0;i<D1;i++){
      float cf = gm*f[i];
      #pragma unroll
      for (int k=0;k<D3;k++) out[k] = fmaf(cf, w3[(i*D2+j)*D3+k], out[k]);
    }
  }
}

__global__ void __launch_bounds__(128) k_output(int blk, int sel){
  const float* fin = sel ? d_feat1 : d_feat0;
  float* fout = sel ? d_feat0 : d_feat1;
  __shared__ float w3s[6292];
  int tid = threadIdx.x;
  int half = blockIdx.y;
  int base = half ? 7026 : 2670;
  int len  = half ? 6292 : 4356;
  for (int i=tid;i<len;i+=128) w3s[i]=d_w3j[base+i];
  __syncthreads();
  int p = blockIdx.x*128 + tid;
  float f4[9], f6[13];
  #pragma unroll
  for (int i=0;i<9;i++) f4[i]=fin[p*22+i];
  #pragma unroll
  for (int i=0;i<13;i++) f6[i]=fin[p*22+9+i];
  const float* cf = d_coef + blk*24;
  if (half==0){
    float d4[9];
    #pragma unroll
    for (int k=0;k<9;k++) d4[k]=0.f;
    qpath<9,9,9>   (w3s+0,    f4, p, cf[0], cf[1], cf[2],  0, 9,18, d4);
    qpath<9,13,9>  (w3s+729,  f4, p, cf[3], cf[4], cf[5], 27,40,53, d4);
    qpath<13,9,9>  (w3s+1782, f6, p, cf[6], cf[7], cf[8],  0, 9,18, d4);
    qpath<13,13,9> (w3s+2835, f6, p, cf[9], cf[10],cf[11],27,40,53, d4);
    #pragma unroll
    for (int k=0;k<9;k++) fout[p*22+k] = f4[k]+d4[k];
  } else {
    float d6[13];
    #pragma unroll
    for (int k=0;k<13;k++) d6[k]=0.f;
    qpath<9,9,13>  (w3s+0,    f4, p, cf[12],cf[13],cf[14], 0, 9,18, d6);
    qpath<9,13,13> (w3s+1053, f4, p, cf[15],cf[16],cf[17],27,40,53, d6);
    qpath<13,9,13> (w3s+2574, f6, p, cf[18],cf[19],cf[20], 0, 9,18, d6);
    qpath<13,13,13>(w3s+4095, f6, p, cf[21],cf[22],cf[23],27,40,53, d6);
    #pragma unroll
    for (int k=0;k<13;k++) fout[p*22+9+k] = f6[k]+d6[k];
  }
}

// ---------------- upsample ----------------
__global__ void k_upsample(const float* __restrict__ upw, float* __restrict__ out){
  int idx = blockIdx.x*256 + threadIdx.x;
  if (idx >= NBATCH*65536) return;
  int b = idx >> 16;
  int nh = idx & 65535;
  int rw = nh & 3; int t = nh >> 2; int w = t & 63; t >>= 6; int rh = t & 3; int h = t >> 2;
  int p = b*NLR + h*64 + w;
  float u4 = upw[(rh*4+rw)*2 + 0];
  float u6 = upw[(rh*4+rw)*2 + 1];
  float* o4 = out + (size_t)idx*9;
  float* o6 = out + 1179648 + (size_t)idx*13;
  #pragma unroll
  for (int k=0;k<9;k++)  o4[k] = d_feat0[p*22+k]*u4;
  #pragma unroll
  for (int k=0;k<13;k++) o6[k] = d_feat0[p*22+9+k]*u6;
}

extern "C" void kernel_launch(void* const* d_in, const int* in_sizes, int n_in,
                              void* d_out, int out_size) {
  const float* f4   = (const float*)d_in[0];
  const float* f6   = (const float*)d_in[1];
  const float* ls4  = (const float*)d_in[2];
  const float* ls6  = (const float*)d_in[3];
  const float* pbw  = (const float*)d_in[4];
  const float* pbb  = (const float*)d_in[5];
  const float* liw4 = (const float*)d_in[6];
  const float* liw6 = (const float*)d_in[7];
  const float* tvw  = (const float*)d_in[8];
  const float* tow  = (const float*)d_in[9];
  const float* low4 = (const float*)d_in[10];
  const float* low6 = (const float*)d_in[11];
  const float* upw  = (const float*)d_in[12];
  float* out = (float*)d_out;

  k_w3j<<<14,256>>>();
  k_shcoef<<<17,256>>>(pbw, pbb, liw4, liw6, tvw, tow, low4, low6);
  for (int blk=0; blk<2; blk++){
    k_prepare<<<128,64>>>(f4, f6, ls4, ls6, blk, blk&1);
    k_attn<<<dim3(NLR/RT, NBATCH, SPLITS), 256>>>();
    k_reduce<<<NPTS/8,256>>>();
    k_output<<<dim3(64,2),128>>>(blk, blk&1);
  }
  k_upsample<<<512,256>>>(upw, out);
}